// round 11
// baseline (speedup 1.0000x reference)
#include <cuda_runtime.h>
#include <math.h>

#define KC 192
#define KP (KC / 2)        // 96 cluster pairs
#define NSLOT 8            // atomic sub-slots per cluster (cuts same-address serialization 8x)
#define Q_MIN 0.5f
#define TPB1 256
#define TPB3 256

// ---------------- device scratch (no allocations allowed) ----------------
// Each (cluster, sub-slot) accumulator 1024B-strided -> distinct L2 partition.
__device__ unsigned long long g_key [KC * NSLOT * 128];  // idx = (k*NSLOT+s)*128
__device__ float              g_wsum[KC * NSLOT * 256];  // idx = (k*NSLOT+s)*256
__device__ float              g_wps [KC * NSLOT * 256];
__device__ float              g_nacc[32 * 256];

// packed cluster pairs: g_Bp[2j]={{Bx2j,Bx2j+1},{By..}}, g_Bp[2j+1]={{Bz..},{Bw..}}
__device__ ulonglong2 g_Bp[KP * 2];
__device__ float2     g_qp[KP];
__device__ float      g_qsum;

// 0 att, 1 rep, 2 minb, 3 pay, 4 noise_sum, 5 noise_cnt, 6 nobj
__device__ float g_s[8];
__device__ unsigned g_done1, g_done2;

// ---------------- helpers ----------------
__device__ __forceinline__ float warp_sum(float v) {
    #pragma unroll
    for (int o = 16; o > 0; o >>= 1) v += __shfl_down_sync(0xFFFFFFFFu, v, o);
    return v;
}
__device__ __forceinline__ float clip_beta(float b) {
    return fminf(fmaxf(b, 1e-4f), 1.0f - 1e-4f);
}
__device__ __forceinline__ unsigned long long fma2(unsigned long long a, unsigned long long b, unsigned long long c) {
    unsigned long long d;
    asm("fma.rn.f32x2 %0, %1, %2, %3;" : "=l"(d) : "l"(a), "l"(b), "l"(c));
    return d;
}
__device__ __forceinline__ unsigned long long add2(unsigned long long a, unsigned long long b) {
    unsigned long long d;
    asm("add.rn.f32x2 %0, %1, %2;" : "=l"(d) : "l"(a), "l"(b));
    return d;
}
__device__ __forceinline__ unsigned long long packf2(float lo, float hi) {
    return (unsigned long long)__float_as_uint(lo) | ((unsigned long long)__float_as_uint(hi) << 32);
}
__device__ __forceinline__ float lo32(unsigned long long v) { return __uint_as_float((unsigned)v); }
__device__ __forceinline__ float hi32(unsigned long long v) { return __uint_as_float((unsigned)(v >> 32)); }
__device__ __forceinline__ float fsqrt_ap(float x) {
    float r; asm("sqrt.approx.f32 %0, %1;" : "=f"(r) : "f"(x)); return r;
}
__device__ __forceinline__ unsigned long long umaxll(unsigned long long a, unsigned long long b) {
    return a > b ? a : b;
}

// ---------------- pass 1: per-point reductions + fused cluster stage ----------------
__global__ void __launch_bounds__(TPB1) k_pass1(const float* __restrict__ pbeta,
                        const float* __restrict__ tenergy,
                        const float* __restrict__ penergy,
                        const float* __restrict__ tpos,
                        const float* __restrict__ ppos,
                        const int*   __restrict__ tidx,
                        const float* __restrict__ cc,
                        const float* __restrict__ ttime,
                        int n)
{
    int t = threadIdx.x;
    int i = blockIdx.x * TPB1 + t;
    int slot = blockIdx.x & (NSLOT - 1);
    float nsum = 0.0f, ncnt = 0.0f;
    if (i < n) {
        float b = clip_beta(pbeta[i]);
        int k = tidx[i];
        if (k >= 0) {
            float a = atanhf(b);
            float w = a * a;
            int base = k * NSLOT + slot;
            unsigned long long key =
                ((unsigned long long)__float_as_uint(b) << 32) |
                (unsigned long long)(0xFFFFFFFFu - (unsigned)i);
            atomicMax(&g_key[base * 128], key);
            atomicAdd(&g_wsum[base * 256], w);

            float te = tenergy[i], pe = penergy[i];
            float de = te - pe;
            float el = (de * de) / (te * te);

            float2 tp = ((const float2*)tpos)[i];
            float2 pp = ((const float2*)ppos)[i];
            float d0 = tp.x - pp.x, d1 = tp.y - pp.y;
            float pl = (d0 * d0) / (tp.x * tp.x) + (d1 * d1) / (tp.y * tp.y);

            atomicAdd(&g_wps[base * 256], w * (el + pl));
        } else {
            nsum = b; ncnt = 1.0f;
        }
    }

    // block-reduce noise, scatter to 32 padded slots
    __shared__ float nred[2][8];
    {
        float ws = warp_sum(nsum), wc = warp_sum(ncnt);
        int wid = t >> 5, lid = t & 31;
        if (lid == 0) { nred[0][wid] = ws; nred[1][wid] = wc; }
        __syncthreads();
        if (wid == 0) {
            float vs = (lid < 8) ? nred[0][lid] : 0.0f;
            float vc = (lid < 8) ? nred[1][lid] : 0.0f;
            vs = warp_sum(vs); vc = warp_sum(vc);
            if (lid == 0 && (vs != 0.0f || vc != 0.0f)) {
                int s = (blockIdx.x & 31) * 256;
                atomicAdd(&g_nacc[s], vs);
                atomicAdd(&g_nacc[s + 1], vc);
            }
        }
    }

    // finisher block: fused cluster stage
    __shared__ int sLast;
    if (t == 0) {
        __threadfence();
        unsigned old = atomicAdd(&g_done1, 1u);
        sLast = (old == gridDim.x - 1) ? 1 : 0;
    }
    __syncthreads();
    if (!sLast) return;
    if (t == 0) __threadfence();
    __syncthreads();

    __shared__ float sb[5][KC];   // Bx By Bz Bw q staging for pair packing
    float minb = 0.0f, pay = 0.0f, nobj = 0.0f, qs = 0.0f;
    if (t < KC) {
        // fold the NSLOT sub-slots
        unsigned long long key = 0ull;
        float ws = 0.0f, wp = 0.0f;
        #pragma unroll
        for (int s = 0; s < NSLOT; s++) {
            int base = t * NSLOT + s;
            key = umaxll(key, g_key[base * 128]);
            ws += g_wsum[base * 256];
            wp += g_wps[base * 256];
            // reset for next replay
            g_key[base * 128] = 0ull;
            g_wsum[base * 256] = 0.0f;
            g_wps[base * 256] = 0.0f;
        }
        float Bx = 0.f, By = 0.f, Bz = 0.f, Bw = 0.f, q = 0.f;
        if (key != 0ull) {
            unsigned idx = 0xFFFFFFFFu - (unsigned)(key & 0xFFFFFFFFull);
            float b = clip_beta(pbeta[idx]);
            float a = atanhf(b);
            q = (a * a + Q_MIN) * ttime[idx];
            float ax = cc[3 * idx], ay = cc[3 * idx + 1], az = cc[3 * idx + 2];
            Bx = -2.0f * ax; By = -2.0f * ay; Bz = -2.0f * az;
            Bw = ax * ax + ay * ay + az * az;
            nobj = 1.0f;
            minb = 1.0f - b;
            qs = q;
            pay = wp / (ws + 1e-9f);
        }
        sb[0][t] = Bx; sb[1][t] = By; sb[2][t] = Bz; sb[3][t] = Bw; sb[4][t] = q;
    }
    // noise slot aggregation + reset
    if (t < 32) {
        float vs = g_nacc[t * 256];
        float vc = g_nacc[t * 256 + 1];
        g_nacc[t * 256] = 0.0f;
        g_nacc[t * 256 + 1] = 0.0f;
        vs = warp_sum(vs); vc = warp_sum(vc);
        if (t == 0) { g_s[4] = vs; g_s[5] = vc; g_done1 = 0u; }
    }
    __syncthreads();
    // pack cluster pairs
    if (t < KP) {
        int a = 2 * t, b = 2 * t + 1;
        g_Bp[2 * t]     = make_ulonglong2(packf2(sb[0][a], sb[0][b]), packf2(sb[1][a], sb[1][b]));
        g_Bp[2 * t + 1] = make_ulonglong2(packf2(sb[2][a], sb[2][b]), packf2(sb[3][a], sb[3][b]));
        g_qp[t] = make_float2(sb[4][a], sb[4][b]);
    }
    // reduce minb / pay / nobj / Qsum over 8 warps
    __shared__ float red[4][8];
    float wm = warp_sum(minb), wp2 = warp_sum(pay), wn = warp_sum(nobj), wq = warp_sum(qs);
    int wid = t >> 5, lid = t & 31;
    if (lid == 0) { red[0][wid] = wm; red[1][wid] = wp2; red[2][wid] = wn; red[3][wid] = wq; }
    __syncthreads();
    if (wid == 0) {
        float vm = (lid < 8) ? red[0][lid] : 0.0f;
        float vp = (lid < 8) ? red[1][lid] : 0.0f;
        float vn = (lid < 8) ? red[2][lid] : 0.0f;
        float vq = (lid < 8) ? red[3][lid] : 0.0f;
        vm = warp_sum(vm); vp = warp_sum(vp); vn = warp_sum(vn); vq = warp_sum(vq);
        if (lid == 0) { g_s[2] = vm; g_s[3] = vp; g_s[6] = vn; g_qsum = vq; }
    }
}

// ---------------- pass 2: O(N*K) pair pass (R5 form: shared table) ----------------
__global__ void __launch_bounds__(TPB3) k_main(const float* __restrict__ pbeta,
                                               const float* __restrict__ cc,
                                               const float* __restrict__ ttime,
                                               const int*   __restrict__ tidx,
                                               int n, float* __restrict__ out)
{
    __shared__ ulonglong2 sB[KP * 2];
    __shared__ float2 sQp[KP];
    __shared__ float sQsum;
    __shared__ float red[16];
    __shared__ int sLast;

    int t = threadIdx.x;
    for (int j = t; j < KP * 2; j += TPB3) sB[j] = g_Bp[j];
    for (int j = t; j < KP; j += TPB3) sQp[j] = g_qp[j];
    if (t == 0) sQsum = g_qsum;
    __syncthreads();

    int i = blockIdx.x * TPB3 + t;

    float x0 = 0.f, x1 = 0.f, x2 = 0.f, q = 0.f; int km = -1;
    if (i < n) {
        x0 = cc[3 * i]; x1 = cc[3 * i + 1]; x2 = cc[3 * i + 2];
        float b = clip_beta(pbeta[i]); float a = atanhf(b);
        q = (a * a + Q_MIN) * ttime[i];
        km = tidx[i];
    }
    float ci = fmaf(x2, x2, fmaf(x1, x1, fmaf(x0, x0, 1e-9f)));

    unsigned long long x0d = packf2(x0, x0);
    unsigned long long x1d = packf2(x1, x1);
    unsigned long long x2d = packf2(x2, x2);
    unsigned long long cid = packf2(ci, ci);

    float accA = 0.0f, accB = 0.0f;
    #pragma unroll 4
    for (int j = 0; j < KP; j++) {
        ulonglong2 ba = sB[2 * j];       // {Bx lo,hi},{By lo,hi}
        ulonglong2 bb = sB[2 * j + 1];   // {Bz lo,hi},{Bw lo,hi}
        float2 qp = sQp[j];
        unsigned long long tt = fma2(ba.x, x0d, cid);
        tt = fma2(ba.y, x1d, tt);
        tt = fma2(bb.x, x2d, tt);
        unsigned long long d2p = add2(tt, bb.y);
        // saturate clamps cancellation-negative d2 to 0 (sqrt(neg) would be NaN)
        accA = fmaf(qp.x, fsqrt_ap(__saturatef(lo32(d2p))), accA);
        accB = fmaf(qp.y, fsqrt_ap(__saturatef(hi32(d2p))), accB);
    }

    float att = 0.0f, rep = 0.0f;
    {
        float def = sQsum - (accA + accB);
        if (km >= 0) {
            int j = km >> 1; int hi = km & 1;
            ulonglong2 ba = sB[2 * j], bb = sB[2 * j + 1];
            float Bx = hi ? hi32(ba.x) : lo32(ba.x);
            float By = hi ? hi32(ba.y) : lo32(ba.y);
            float Bz = hi ? hi32(bb.x) : lo32(bb.x);
            float Bw = hi ? hi32(bb.y) : lo32(bb.y);
            float2 qp = sQp[j];
            float qm = hi ? qp.y : qp.x;
            float tm = fmaf(Bx, x0, ci); tm = fmaf(By, x1, tm); tm = fmaf(Bz, x2, tm);
            float d2e = tm + Bw;
            float m = fsqrt_ap(__saturatef(d2e));
            def -= qm * (1.0f - m);
            att = (d2e - 1e-9f) * qm * q;
        }
        rep = q * def;
    }

    // block reduce (8 warps)
    float wa = warp_sum(att), wr = warp_sum(rep);
    int wid = t >> 5, lid = t & 31;
    if (lid == 0) { red[wid] = wa; red[8 + wid] = wr; }
    __syncthreads();
    if (wid == 0) {
        float va = (lid < 8) ? red[lid]     : 0.0f;
        float vr = (lid < 8) ? red[8 + lid] : 0.0f;
        va = warp_sum(va); vr = warp_sum(vr);
        if (lid == 0) { atomicAdd(&g_s[0], va); atomicAdd(&g_s[1], vr); }
    }

    // finisher: compute output, re-zero accumulators for next replay
    if (t == 0) {
        __threadfence();
        unsigned old = atomicAdd(&g_done2, 1u);
        sLast = (old == gridDim.x - 1) ? 1 : 0;
    }
    __syncthreads();
    if (sLast && t == 0) {
        __threadfence();
        volatile float* vs = g_s;
        float s0 = vs[0], s1 = vs[1], s2 = vs[2], s3 = vs[3];
        float s4 = vs[4], s5 = vs[5], s6 = vs[6];
        float nobj = fmaxf(s6, 1.0f);
        float ncnt = fmaxf(s5, 1.0f);
        out[0] = (s0 + s1) / (float)n + s2 / nobj + s4 / ncnt + s3 / nobj;
        g_s[0] = 0.0f; g_s[1] = 0.0f;
        g_done2 = 0u;
    }
}

// ---------------- launcher ----------------
// metadata order: 0 pred_beta, 1 pred_ccoords, 2 pred_energy, 3 pred_pos,
// 4 pred_time, 5 pred_id, 6 t_idx, 7 t_energy, 8 t_pos, 9 t_time, 10 t_pid, 11 rowsplits
extern "C" void kernel_launch(void* const* d_in, const int* in_sizes, int n_in,
                              void* d_out, int out_size) {
    const float* pbeta   = (const float*)d_in[0];
    const float* cc      = (const float*)d_in[1];
    const float* penergy = (const float*)d_in[2];
    const float* ppos    = (const float*)d_in[3];
    const int*   tidx    = (const int*)  d_in[6];
    const float* tenergy = (const float*)d_in[7];
    const float* tpos    = (const float*)d_in[8];
    const float* ttime   = (const float*)d_in[9];
    float* out = (float*)d_out;

    int n = in_sizes[0];
    int blocks1 = (n + TPB1 - 1) / TPB1;
    int blocks3 = (n + TPB3 - 1) / TPB3;

    k_pass1<<<blocks1, TPB1>>>(pbeta, tenergy, penergy, tpos, ppos, tidx, cc, ttime, n);
    k_main<<<blocks3, TPB3>>>(pbeta, cc, ttime, tidx, n, out);
}

// round 12
// speedup vs baseline: 1.3129x; 1.3129x over previous
#include <cuda_runtime.h>
#include <math.h>

#define KC 192
#define KP (KC / 2)        // 96 cluster pairs
#define Q_MIN 0.5f
#define TPB1 256
#define TPB3 256

// ---------------- device scratch (no allocations allowed) ----------------
// Atomic targets 1024B-strided so each lands on a distinct L2 partition.
__device__ unsigned long long g_key[KC * 128];   // stride 128 ull = 1024B
__device__ float2 g_wsp[KC * 128];               // {wsum, w*(el+pl)}, stride 128 float2 = 1024B
__device__ float g_nacc[32 * 256];

// packed cluster pairs: g_Bp[2j] = {{Bx2j,Bx2j+1},{By..}}, g_Bp[2j+1] = {{Bz..},{Bw..}}
__device__ ulonglong2 g_Bp[KP * 2];
__device__ float2     g_qp[KP];
__device__ float      g_qsum;

// 0 att, 1 rep, 2 minb, 3 pay, 4 noise_sum, 5 noise_cnt, 6 nobj
__device__ float g_s[8];
__device__ unsigned g_done1, g_done2;

// ---------------- helpers ----------------
__device__ __forceinline__ float warp_sum(float v) {
    #pragma unroll
    for (int o = 16; o > 0; o >>= 1) v += __shfl_down_sync(0xFFFFFFFFu, v, o);
    return v;
}
__device__ __forceinline__ float clip_beta(float b) {
    return fminf(fmaxf(b, 1e-4f), 1.0f - 1e-4f);
}
__device__ __forceinline__ unsigned long long fma2(unsigned long long a, unsigned long long b, unsigned long long c) {
    unsigned long long d;
    asm("fma.rn.f32x2 %0, %1, %2, %3;" : "=l"(d) : "l"(a), "l"(b), "l"(c));
    return d;
}
__device__ __forceinline__ unsigned long long add2(unsigned long long a, unsigned long long b) {
    unsigned long long d;
    asm("add.rn.f32x2 %0, %1, %2;" : "=l"(d) : "l"(a), "l"(b));
    return d;
}
__device__ __forceinline__ unsigned long long packf2(float lo, float hi) {
    return (unsigned long long)__float_as_uint(lo) | ((unsigned long long)__float_as_uint(hi) << 32);
}
__device__ __forceinline__ float lo32(unsigned long long v) { return __uint_as_float((unsigned)v); }
__device__ __forceinline__ float hi32(unsigned long long v) { return __uint_as_float((unsigned)(v >> 32)); }
__device__ __forceinline__ float fsqrt_ap(float x) {
    float r; asm("sqrt.approx.f32 %0, %1;" : "=f"(r) : "f"(x)); return r;
}
// packed f32x2 reduction: one RED instruction for both accumulators (sm_90+)
__device__ __forceinline__ void red_add_v2(float2* addr, float a, float b) {
    asm volatile("red.global.add.v2.f32 [%0], {%1, %2};" :: "l"(addr), "f"(a), "f"(b) : "memory");
}

// ---------------- pass 1: per-point reductions + fused cluster stage ----------------
__global__ void __launch_bounds__(TPB1) k_pass1(const float* __restrict__ pbeta,
                        const float* __restrict__ tenergy,
                        const float* __restrict__ penergy,
                        const float* __restrict__ tpos,
                        const float* __restrict__ ppos,
                        const int*   __restrict__ tidx,
                        const float* __restrict__ cc,
                        const float* __restrict__ ttime,
                        int n)
{
    int t = threadIdx.x;
    int i = blockIdx.x * TPB1 + t;
    float nsum = 0.0f, ncnt = 0.0f;
    if (i < n) {
        float b = clip_beta(pbeta[i]);
        int k = tidx[i];
        if (k >= 0) {
            float a = atanhf(b);
            float w = a * a;
            unsigned long long key =
                ((unsigned long long)__float_as_uint(b) << 32) |
                (unsigned long long)(0xFFFFFFFFu - (unsigned)i);
            atomicMax(&g_key[k * 128], key);

            float te = tenergy[i], pe = penergy[i];
            float de = te - pe;
            float el = (de * de) / (te * te);

            float2 tp = ((const float2*)tpos)[i];
            float2 pp = ((const float2*)ppos)[i];
            float d0 = tp.x - pp.x, d1 = tp.y - pp.y;
            float pl = (d0 * d0) / (tp.x * tp.x) + (d1 * d1) / (tp.y * tp.y);

            // single packed RED for {wsum, w*(el+pl)}
            red_add_v2(&g_wsp[k * 128], w, w * (el + pl));
        } else {
            nsum = b; ncnt = 1.0f;
        }
    }

    // block-reduce noise, scatter to 32 padded slots
    __shared__ float nred[2][8];
    {
        float ws = warp_sum(nsum), wc = warp_sum(ncnt);
        int wid = t >> 5, lid = t & 31;
        if (lid == 0) { nred[0][wid] = ws; nred[1][wid] = wc; }
        __syncthreads();
        if (wid == 0) {
            float vs = (lid < 8) ? nred[0][lid] : 0.0f;
            float vc = (lid < 8) ? nred[1][lid] : 0.0f;
            vs = warp_sum(vs); vc = warp_sum(vc);
            if (lid == 0 && (vs != 0.0f || vc != 0.0f)) {
                int s = (blockIdx.x & 31) * 256;
                atomicAdd(&g_nacc[s], vs);
                atomicAdd(&g_nacc[s + 1], vc);
            }
        }
    }

    // finisher block: fused cluster stage
    __shared__ int sLast;
    if (t == 0) {
        __threadfence();
        unsigned old = atomicAdd(&g_done1, 1u);
        sLast = (old == gridDim.x - 1) ? 1 : 0;
    }
    __syncthreads();
    if (!sLast) return;
    if (t == 0) __threadfence();
    __syncthreads();

    __shared__ float sb[5][KC];   // Bx By Bz Bw q staging for pair packing
    float minb = 0.0f, pay = 0.0f, nobj = 0.0f, qs = 0.0f;
    if (t < KC) {
        unsigned long long key = g_key[t * 128];
        float2 wsp = g_wsp[t * 128];
        float Bx = 0.f, By = 0.f, Bz = 0.f, Bw = 0.f, q = 0.f;
        if (key != 0ull) {
            unsigned idx = 0xFFFFFFFFu - (unsigned)(key & 0xFFFFFFFFull);
            float b = clip_beta(pbeta[idx]);
            float a = atanhf(b);
            q = (a * a + Q_MIN) * ttime[idx];
            float ax = cc[3 * idx], ay = cc[3 * idx + 1], az = cc[3 * idx + 2];
            Bx = -2.0f * ax; By = -2.0f * ay; Bz = -2.0f * az;
            Bw = ax * ax + ay * ay + az * az;
            nobj = 1.0f;
            minb = 1.0f - b;
            qs = q;
            pay = wsp.y / (wsp.x + 1e-9f);
        }
        sb[0][t] = Bx; sb[1][t] = By; sb[2][t] = Bz; sb[3][t] = Bw; sb[4][t] = q;
        // reset pass-1 scratch for next replay
        g_key[t * 128] = 0ull;
        g_wsp[t * 128] = make_float2(0.0f, 0.0f);
    }
    // noise slot aggregation + reset
    if (t < 32) {
        float vs = g_nacc[t * 256];
        float vc = g_nacc[t * 256 + 1];
        g_nacc[t * 256] = 0.0f;
        g_nacc[t * 256 + 1] = 0.0f;
        vs = warp_sum(vs); vc = warp_sum(vc);
        if (t == 0) { g_s[4] = vs; g_s[5] = vc; g_done1 = 0u; }
    }
    __syncthreads();
    // pack cluster pairs
    if (t < KP) {
        int a = 2 * t, b = 2 * t + 1;
        g_Bp[2 * t]     = make_ulonglong2(packf2(sb[0][a], sb[0][b]), packf2(sb[1][a], sb[1][b]));
        g_Bp[2 * t + 1] = make_ulonglong2(packf2(sb[2][a], sb[2][b]), packf2(sb[3][a], sb[3][b]));
        g_qp[t] = make_float2(sb[4][a], sb[4][b]);
    }
    // reduce minb / pay / nobj / Qsum over 8 warps
    __shared__ float red[4][8];
    float wm = warp_sum(minb), wp = warp_sum(pay), wn = warp_sum(nobj), wq = warp_sum(qs);
    int wid = t >> 5, lid = t & 31;
    if (lid == 0) { red[0][wid] = wm; red[1][wid] = wp; red[2][wid] = wn; red[3][wid] = wq; }
    __syncthreads();
    if (wid == 0) {
        float vm = (lid < 8) ? red[0][lid] : 0.0f;
        float vp = (lid < 8) ? red[1][lid] : 0.0f;
        float vn = (lid < 8) ? red[2][lid] : 0.0f;
        float vq = (lid < 8) ? red[3][lid] : 0.0f;
        vm = warp_sum(vm); vp = warp_sum(vp); vn = warp_sum(vn); vq = warp_sum(vq);
        if (lid == 0) { g_s[2] = vm; g_s[3] = vp; g_s[6] = vn; g_qsum = vq; }
    }
}

// ---------------- pass 2: O(N*K) pair pass (R5 form: shared table) ----------------
__global__ void __launch_bounds__(TPB3) k_main(const float* __restrict__ pbeta,
                                               const float* __restrict__ cc,
                                               const float* __restrict__ ttime,
                                               const int*   __restrict__ tidx,
                                               int n, float* __restrict__ out)
{
    __shared__ ulonglong2 sB[KP * 2];
    __shared__ float2 sQp[KP];
    __shared__ float sQsum;
    __shared__ float red[16];
    __shared__ int sLast;

    int t = threadIdx.x;
    for (int j = t; j < KP * 2; j += TPB3) sB[j] = g_Bp[j];
    for (int j = t; j < KP; j += TPB3) sQp[j] = g_qp[j];
    if (t == 0) sQsum = g_qsum;
    __syncthreads();

    int i = blockIdx.x * TPB3 + t;

    float x0 = 0.f, x1 = 0.f, x2 = 0.f, q = 0.f; int km = -1;
    if (i < n) {
        x0 = cc[3 * i]; x1 = cc[3 * i + 1]; x2 = cc[3 * i + 2];
        float b = clip_beta(pbeta[i]); float a = atanhf(b);
        q = (a * a + Q_MIN) * ttime[i];
        km = tidx[i];
    }
    float ci = fmaf(x2, x2, fmaf(x1, x1, fmaf(x0, x0, 1e-9f)));

    unsigned long long x0d = packf2(x0, x0);
    unsigned long long x1d = packf2(x1, x1);
    unsigned long long x2d = packf2(x2, x2);
    unsigned long long cid = packf2(ci, ci);

    float accA = 0.0f, accB = 0.0f;
    #pragma unroll 4
    for (int j = 0; j < KP; j++) {
        ulonglong2 ba = sB[2 * j];       // {Bx lo,hi},{By lo,hi}
        ulonglong2 bb = sB[2 * j + 1];   // {Bz lo,hi},{Bw lo,hi}
        float2 qp = sQp[j];
        unsigned long long tt = fma2(ba.x, x0d, cid);
        tt = fma2(ba.y, x1d, tt);
        tt = fma2(bb.x, x2d, tt);
        unsigned long long d2p = add2(tt, bb.y);
        // saturate clamps cancellation-negative d2 to 0 (sqrt(neg) would be NaN)
        accA = fmaf(qp.x, fsqrt_ap(__saturatef(lo32(d2p))), accA);
        accB = fmaf(qp.y, fsqrt_ap(__saturatef(hi32(d2p))), accB);
    }

    float att = 0.0f, rep = 0.0f;
    {
        float def = sQsum - (accA + accB);
        if (km >= 0) {
            int j = km >> 1; int hi = km & 1;
            ulonglong2 ba = sB[2 * j], bb = sB[2 * j + 1];
            float Bx = hi ? hi32(ba.x) : lo32(ba.x);
            float By = hi ? hi32(ba.y) : lo32(ba.y);
            float Bz = hi ? hi32(bb.x) : lo32(bb.x);
            float Bw = hi ? hi32(bb.y) : lo32(bb.y);
            float2 qp = sQp[j];
            float qm = hi ? qp.y : qp.x;
            float tm = fmaf(Bx, x0, ci); tm = fmaf(By, x1, tm); tm = fmaf(Bz, x2, tm);
            float d2e = tm + Bw;
            float m = fsqrt_ap(__saturatef(d2e));
            def -= qm * (1.0f - m);
            att = (d2e - 1e-9f) * qm * q;
        }
        rep = q * def;
    }

    // block reduce (8 warps)
    float wa = warp_sum(att), wr = warp_sum(rep);
    int wid = t >> 5, lid = t & 31;
    if (lid == 0) { red[wid] = wa; red[8 + wid] = wr; }
    __syncthreads();
    if (wid == 0) {
        float va = (lid < 8) ? red[lid]     : 0.0f;
        float vr = (lid < 8) ? red[8 + lid] : 0.0f;
        va = warp_sum(va); vr = warp_sum(vr);
        if (lid == 0) { atomicAdd(&g_s[0], va); atomicAdd(&g_s[1], vr); }
    }

    // finisher: compute output, re-zero accumulators for next replay
    if (t == 0) {
        __threadfence();
        unsigned old = atomicAdd(&g_done2, 1u);
        sLast = (old == gridDim.x - 1) ? 1 : 0;
    }
    __syncthreads();
    if (sLast && t == 0) {
        __threadfence();
        volatile float* vs = g_s;
        float s0 = vs[0], s1 = vs[1], s2 = vs[2], s3 = vs[3];
        float s4 = vs[4], s5 = vs[5], s6 = vs[6];
        float nobj = fmaxf(s6, 1.0f);
        float ncnt = fmaxf(s5, 1.0f);
        out[0] = (s0 + s1) / (float)n + s2 / nobj + s4 / ncnt + s3 / nobj;
        g_s[0] = 0.0f; g_s[1] = 0.0f;
        g_done2 = 0u;
    }
}

// ---------------- launcher ----------------
// metadata order: 0 pred_beta, 1 pred_ccoords, 2 pred_energy, 3 pred_pos,
// 4 pred_time, 5 pred_id, 6 t_idx, 7 t_energy, 8 t_pos, 9 t_time, 10 t_pid, 11 rowsplits
extern "C" void kernel_launch(void* const* d_in, const int* in_sizes, int n_in,
                              void* d_out, int out_size) {
    const float* pbeta   = (const float*)d_in[0];
    const float* cc      = (const float*)d_in[1];
    const float* penergy = (const float*)d_in[2];
    const float* ppos    = (const float*)d_in[3];
    const int*   tidx    = (const int*)  d_in[6];
    const float* tenergy = (const float*)d_in[7];
    const float* tpos    = (const float*)d_in[8];
    const float* ttime   = (const float*)d_in[9];
    float* out = (float*)d_out;

    int n = in_sizes[0];
    int blocks1 = (n + TPB1 - 1) / TPB1;
    int blocks3 = (n + TPB3 - 1) / TPB3;

    k_pass1<<<blocks1, TPB1>>>(pbeta, tenergy, penergy, tpos, ppos, tidx, cc, ttime, n);
    k_main<<<blocks3, TPB3>>>(pbeta, cc, ttime, tidx, n, out);
}